// round 3
// baseline (speedup 1.0000x reference)
#include <cuda_runtime.h>
#include <cstdint>

// ---------------- problem constants ----------------
#define Dd   1024
#define Hh   16
#define DHd  64
#define Bb   4
#define Nn   1024
#define Ee   (2*Dd + DHd)      // 2112
#define TOK  (Bb*Nn)           // 4096

// ---------------- scratch (device globals; no allocs allowed) ----------------
__device__ float g_M   [(size_t)Hh*Dd*Dd];     //  64 MB   M_h = Wq_h @ Wk_h^T
__device__ float g_t   [(size_t)Hh*TOK*Dd];    // 256 MB   t = x @ M_h      [h][b*N+n][j]
__device__ float g_Araw[(size_t)Bb*Hh*Nn*Nn];  // 256 MB   scores/probs     [b*H+h][n][m]
__device__ float g_v   [(size_t)Hh*TOK*DHd];   //  16 MB   v                [h][b*N+m][dh]
__device__ float g_sa  [(size_t)TOK*Dd];       //  16 MB   sa               [b*N+n][h*DH+dh]
__device__ float g_u   [Hh*Dd];
__device__ float g_w   [Hh*Dd];
__device__ float g_c   [Hh];
__device__ float g_rq  [Bb*Hh*Nn];
__device__ float g_rk  [Bb*Hh*Nn];

// ---------------- tf32 helpers ----------------
__device__ __forceinline__ uint32_t f2tf32(float f) {
    uint32_t u;
    asm("cvt.rna.tf32.f32 %0, %1;" : "=r"(u) : "f"(f));
    return u;
}

__device__ __forceinline__ void mma_tf32(float* d, const uint32_t* a, const uint32_t* b) {
    asm volatile(
        "mma.sync.aligned.m16n8k8.row.col.f32.tf32.tf32.f32 "
        "{%0,%1,%2,%3}, {%4,%5,%6,%7}, {%8,%9}, {%0,%1,%2,%3};\n"
        : "+f"(d[0]), "+f"(d[1]), "+f"(d[2]), "+f"(d[3])
        : "r"(a[0]), "r"(a[1]), "r"(a[2]), "r"(a[3]),
          "r"(b[0]), "r"(b[1]));
}

__device__ __forceinline__ void cpa16(float* dst, const float* src, bool full) {
    uint32_t d = (uint32_t)__cvta_generic_to_shared(dst);
    int sz = full ? 16 : 0;
    asm volatile("cp.async.cg.shared.global [%0], [%1], 16, %2;\n"
                 :: "r"(d), "l"(src), "r"(sz));
}
__device__ __forceinline__ void cp_commit() {
    asm volatile("cp.async.commit_group;\n");
}
template<int N>
__device__ __forceinline__ void cp_wait() {
    asm volatile("cp.async.wait_group %0;\n" :: "n"(N));
}

// ---------------- generic batched GEMM (tf32 tensor cores, cp.async 3-stage) ----
// C[z][m][n] = sum_k A[m,k] * B[k,n]  (+ bias[n])
// A is always [M,K] k-contiguous with row stride as_m.
// B: b_kcontig=1 -> B[n][k] k-contiguous, row stride bs_row (n rows)
//    b_kcontig=0 -> B[k][n] n-contiguous, row stride bs_row (k rows)
struct GemmP {
    const float* A; const float* B; float* C; const float* bias;
    int as_m, bs_row, cs_m;
    int b_kcontig;
    long long a_so, a_si, b_so, b_si, c_so, c_si, bias_so;
    int M, N, K, zdiv;
    int causal;   // skip CTAs fully above the diagonal (C[n][m], m>n)
    int klimit;   // K_eff = min(K, m0+BM)  (A rows n only need k=m <= n)
};

#define BM 128
#define BN 128
#define BK 32
#define ASTR 36     // A smem row stride (floats): bank-conflict-free pad
#define BSTR_KC 36  // B smem row stride, k-contig layout [n][k]
#define BSTR_NC 136 // B smem row stride, n-contig layout [k][n]
#define A_TILE (BM*ASTR)               // 4608 floats
#define B_TILE 4608                    // max(128*36, 32*136)=4608 floats
#define STAGES 3
#define SMEM_FLOATS (STAGES*(A_TILE + B_TILE))   // 27648 floats = 110592 B

__global__ __launch_bounds__(256) void gemm_tf32_kernel(GemmP p) {
    extern __shared__ float smem[];

    if (p.causal && ((int)blockIdx.x > (int)blockIdx.y)) return;

    const int z  = blockIdx.z;
    const long long zo = z / p.zdiv;
    const long long zi = z % p.zdiv;

    const float* Ab = p.A + zo * p.a_so + zi * p.a_si;
    const float* Bv = p.B + zo * p.b_so + zi * p.b_si;
    float*       Cb = p.C + zo * p.c_so + zi * p.c_si;

    const int m0 = blockIdx.y * BM;
    const int n0 = blockIdx.x * BN;

    const int tid  = threadIdx.x;
    const int warp = tid >> 5;
    const int lane = tid & 31;
    const int wm   = (warp >> 2) * 64;   // warp grid 2 x 4 over 128 x 128
    const int wn   = (warp & 3)  * 32;
    const int grp  = lane >> 2;          // 0..7
    const int t4   = lane & 3;           // 0..3

    const int K_eff = p.klimit ? min(p.K, m0 + BM) : p.K;
    const int nIter = K_eff / BK;

    // ---- per-thread loader coordinates ----
    // A tile: 128 rows x 8 chunks of 16B
    const int a_m  = tid >> 3;
    const int a_kc = (tid & 7) * 4;
    const float* a_src0 = Ab + (size_t)(m0 + a_m) * p.as_m + a_kc;
    // B k-contig: 128 n-rows x 8 chunks
    const int bk_n  = tid >> 3;
    const int bk_kc = (tid & 7) * 4;
    const float* bk_src0 = Bv + (size_t)(n0 + bk_n) * p.bs_row + bk_kc;
    // B n-contig: 32 k-rows x 32 chunks
    const int bn_k  = tid >> 5;
    const int bn_nc = (tid & 31) * 4;
    const bool bn_full = (n0 + bn_nc) < p.N;
    const float* bn_src0 = bn_full ? (Bv + (size_t)bn_k * p.bs_row + n0 + bn_nc) : Bv;

    const bool bkc = (p.b_kcontig != 0);

    // issue loads for stage st at k-offset k0
    auto load_tiles = [&](int st, int k0) {
        float* Asb = smem + st * A_TILE;
        {
            const float* src = a_src0 + k0;
            float* dst = Asb + a_m * ASTR + a_kc;
#pragma unroll
            for (int i = 0; i < 4; i++) {
                cpa16(dst, src, true);
                src += (size_t)32 * p.as_m;
                dst += 32 * ASTR;
            }
        }
        float* Bsb = smem + STAGES * A_TILE + st * B_TILE;
        if (bkc) {
            const float* src = bk_src0 + k0;
            float* dst = Bsb + bk_n * BSTR_KC + bk_kc;
#pragma unroll
            for (int i = 0; i < 4; i++) {
                cpa16(dst, src, true);
                src += (size_t)32 * p.bs_row;
                dst += 32 * BSTR_KC;
            }
        } else {
            const float* src = bn_src0 + (size_t)k0 * p.bs_row;
            float* dst = Bsb + bn_k * BSTR_NC + bn_nc;
#pragma unroll
            for (int i = 0; i < 4; i++) {
                cpa16(dst, src, bn_full);
                src += (size_t)8 * p.bs_row;
                dst += 8 * BSTR_NC;
            }
        }
        cp_commit();
    };

    float acc[4][4][4];
#pragma unroll
    for (int i = 0; i < 4; i++)
#pragma unroll
        for (int j = 0; j < 4; j++)
#pragma unroll
            for (int r = 0; r < 4; r++) acc[i][j][r] = 0.f;

    // prologue: prefetch 2 stages
    load_tiles(0, 0);
    load_tiles(1, BK);

    for (int it = 0; it < nIter; it++) {
        const int st = it % STAGES;
        if (it + 2 < nIter) {
            load_tiles((it + 2) % STAGES, (it + 2) * BK);
            cp_wait<2>();
        } else if (it + 1 < nIter) {
            cp_wait<1>();
        } else {
            cp_wait<0>();
        }
        __syncthreads();

        const float* Asb = smem + st * A_TILE;
        const float* Bsb = smem + STAGES * A_TILE + st * B_TILE;

#pragma unroll
        for (int ks = 0; ks < 4; ks++) {
            uint32_t a[4][4];
            uint32_t b[4][2];
#pragma unroll
            for (int mt = 0; mt < 4; mt++) {
                const float* ap = Asb + (wm + mt * 16 + grp) * ASTR + ks * 8 + t4;
                a[mt][0] = f2tf32(ap[0]);
                a[mt][1] = f2tf32(ap[8 * ASTR]);
                a[mt][2] = f2tf32(ap[4]);
                a[mt][3] = f2tf32(ap[8 * ASTR + 4]);
            }
            if (bkc) {
#pragma unroll
                for (int nt = 0; nt < 4; nt++) {
                    const float* bp = Bsb + (wn + nt * 8 + grp) * BSTR_KC + ks * 8 + t4;
                    b[nt][0] = f2tf32(bp[0]);
                    b[nt][1] = f2tf32(bp[4]);
                }
            } else {
#pragma unroll
                for (int nt = 0; nt < 4; nt++) {
                    const float* bp = Bsb + (ks * 8 + t4) * BSTR_NC + wn + nt * 8 + grp;
                    b[nt][0] = f2tf32(bp[0]);
                    b[nt][1] = f2tf32(bp[4 * BSTR_NC]);
                }
            }
#pragma unroll
            for (int mt = 0; mt < 4; mt++)
#pragma unroll
                for (int nt = 0; nt < 4; nt++)
                    mma_tf32(acc[mt][nt], a[mt], b[nt]);
        }
        __syncthreads();
    }

    const float* biasb = nullptr;
    if (p.bias) biasb = p.bias + zo * p.bias_so;

#pragma unroll
    for (int mt = 0; mt < 4; mt++) {
#pragma unroll
        for (int nt = 0; nt < 4; nt++) {
            int c = n0 + wn + nt * 8 + t4 * 2;
            if (c >= p.N) continue;
            float b0 = 0.f, b1 = 0.f;
            if (biasb) { b0 = biasb[c]; b1 = biasb[c + 1]; }
#pragma unroll
            for (int rr = 0; rr < 2; rr++) {
                int row = m0 + wm + mt * 16 + grp + rr * 8;
                float2 v2;
                v2.x = acc[mt][nt][rr * 2]     + b0;
                v2.y = acc[mt][nt][rr * 2 + 1] + b1;
                *reinterpret_cast<float2*>(Cb + (size_t)row * p.cs_m + c) = v2;
            }
        }
    }
}

// ---------------- bias-correction prep kernels (exact handling of bkqv) ----------------
__global__ void prep_uw_kernel(const float* __restrict__ Wkqv, const float* __restrict__ bkqv,
                               float* __restrict__ u, float* __restrict__ w) {
    int gw = (blockIdx.x * blockDim.x + threadIdx.x) >> 5;
    if (gw >= Hh * Dd) return;
    int lane = threadIdx.x & 31;
    int h = gw >> 10;
    int i = gw & (Dd - 1);
    const float* row = Wkqv + ((long long)h * Dd + i) * Ee;
    const float* bh  = bkqv + (long long)h * Ee;
    float s1 = 0.f, s2 = 0.f;
    for (int e = lane; e < Dd; e += 32) {
        s1 += row[Dd + e] * bh[e];
        s2 += row[e]      * bh[Dd + e];
    }
#pragma unroll
    for (int o = 16; o > 0; o >>= 1) {
        s1 += __shfl_xor_sync(0xffffffffu, s1, o);
        s2 += __shfl_xor_sync(0xffffffffu, s2, o);
    }
    if (lane == 0) { u[gw] = s1; w[gw] = s2; }
}

__global__ void prep_c_kernel(const float* __restrict__ bkqv, float* __restrict__ c) {
    int h = threadIdx.x >> 5;
    if (h >= Hh) return;
    int lane = threadIdx.x & 31;
    const float* bh = bkqv + (long long)h * Ee;
    float s = 0.f;
    for (int e = lane; e < Dd; e += 32) s += bh[Dd + e] * bh[e];
#pragma unroll
    for (int o = 16; o > 0; o >>= 1) s += __shfl_xor_sync(0xffffffffu, s, o);
    if (lane == 0) c[h] = s;
}

__global__ void prep_rqrk_kernel(const float* __restrict__ x, const float* __restrict__ u,
                                 const float* __restrict__ w, float* __restrict__ rq,
                                 float* __restrict__ rk) {
    int gw = (blockIdx.x * blockDim.x + threadIdx.x) >> 5;
    if (gw >= TOK * Hh) return;
    int lane = threadIdx.x & 31;
    int h   = gw & (Hh - 1);
    int tok = gw >> 4;
    const float* xr = x + (long long)tok * Dd;
    const float* uh = u + h * Dd;
    const float* wh = w + h * Dd;
    float s1 = 0.f, s2 = 0.f;
    for (int i = lane; i < Dd; i += 32) {
        float xv = xr[i];
        s1 += xv * uh[i];
        s2 += xv * wh[i];
    }
#pragma unroll
    for (int o = 16; o > 0; o >>= 1) {
        s1 += __shfl_xor_sync(0xffffffffu, s1, o);
        s2 += __shfl_xor_sync(0xffffffffu, s2, o);
    }
    if (lane == 0) {
        int b = tok >> 10, n = tok & (Nn - 1);
        int z = b * Hh + h;
        rq[z * Nn + n] = s1;
        rk[z * Nn + n] = s2;
    }
}

// ---------------- causal softmax: A = softmax((raw + rq_n + rk_m + c_h)/32) ----------------
__global__ void softmax_kernel(float* __restrict__ A, const float* __restrict__ rq,
                               const float* __restrict__ rk, const float* __restrict__ cvec) {
    const int row = blockIdx.x;
    const int z = row >> 10;
    const int n = row & (Nn - 1);
    const int h = z & (Hh - 1);
    float* rp = A + (long long)z * Nn * Nn + (long long)n * Nn;
    const float* rkz = rk + z * Nn;
    const float addn = rq[z * Nn + n] + cvec[h];
    const int tid = threadIdx.x;

    float l[4];
    float mx = -1e30f;
#pragma unroll
    for (int i = 0; i < 4; i++) {
        int m = tid + i * 256;
        float v = (m <= n) ? (rp[m] + addn + rkz[m]) * 0.03125f : -1e30f;
        l[i] = v;
        mx = fmaxf(mx, v);
    }
    __shared__ float red[256];
    red[tid] = mx; __syncthreads();
#pragma unroll
    for (int s = 128; s > 0; s >>= 1) {
        if (tid < s) red[tid] = fmaxf(red[tid], red[tid + s]);
        __syncthreads();
    }
    mx = red[0]; __syncthreads();

    float sum = 0.f;
#pragma unroll
    for (int i = 0; i < 4; i++) {
        float e = (l[i] > -1e29f) ? __expf(l[i] - mx) : 0.f;
        l[i] = e;
        sum += e;
    }
    red[tid] = sum; __syncthreads();
#pragma unroll
    for (int s = 128; s > 0; s >>= 1) {
        if (tid < s) red[tid] += red[tid + s];
        __syncthreads();
    }
    const float inv = 1.f / red[0];
#pragma unroll
    for (int i = 0; i < 4; i++) rp[tid + i * 256] = l[i] * inv;
}

// ---------------- launch ----------------
extern "C" void kernel_launch(void* const* d_in, const int* in_sizes, int n_in,
                              void* d_out, int out_size) {
    const float* x    = (const float*)d_in[0];
    const float* Wkqv = (const float*)d_in[1];
    const float* bkqv = (const float*)d_in[2];
    const float* Wp   = (const float*)d_in[3];
    const float* bp   = (const float*)d_in[4];
    float* out = (float*)d_out;

    float *gM, *gt, *gA, *gv, *gsa, *gu, *gw, *gc, *grq, *grk;
    cudaGetSymbolAddress((void**)&gM,  g_M);
    cudaGetSymbolAddress((void**)&gt,  g_t);
    cudaGetSymbolAddress((void**)&gA,  g_Araw);
    cudaGetSymbolAddress((void**)&gv,  g_v);
    cudaGetSymbolAddress((void**)&gsa, g_sa);
    cudaGetSymbolAddress((void**)&gu,  g_u);
    cudaGetSymbolAddress((void**)&gw,  g_w);
    cudaGetSymbolAddress((void**)&gc,  g_c);
    cudaGetSymbolAddress((void**)&grq, g_rq);
    cudaGetSymbolAddress((void**)&grk, g_rk);

    static int smem_set = 0;
    if (!smem_set) {
        cudaFuncSetAttribute(gemm_tf32_kernel,
                             cudaFuncAttributeMaxDynamicSharedMemorySize,
                             SMEM_FLOATS * 4);
        smem_set = 1;
    }
    const int SMEM_B = SMEM_FLOATS * 4;

    // bias-correction prep (exact even though bkqv happens to be zeros)
    prep_uw_kernel<<<(Hh * Dd * 32 + 255) / 256, 256>>>(Wkqv, bkqv, gu, gw);
    prep_c_kernel<<<1, 512>>>(bkqv, gc);
    prep_rqrk_kernel<<<(TOK * Hh * 32 + 255) / 256, 256>>>(x, gu, gw, grq, grk);

    // K1: M_h = Wq_h @ Wk_h^T   (per head: 1024x1024x1024)
    {
        GemmP p{};
        p.A = Wkqv + Dd; p.as_m = Ee; p.a_so = (long long)Dd * Ee; p.a_si = 0;
        p.B = Wkqv; p.b_kcontig = 1; p.bs_row = Ee;
        p.b_so = (long long)Dd * Ee; p.b_si = 0;
        p.C = gM; p.cs_m = Dd; p.c_so = (long long)Dd * Dd; p.c_si = 0;
        p.bias = nullptr; p.bias_so = 0;
        p.M = Dd; p.N = Dd; p.K = Dd; p.zdiv = 1; p.causal = 0; p.klimit = 0;
        gemm_tf32_kernel<<<dim3(8, 8, Hh), 256, SMEM_B>>>(p);
    }
    // K2: t_h = X @ M_h   (per head: 4096x1024x1024)
    {
        GemmP p{};
        p.A = x; p.as_m = Dd; p.a_so = 0; p.a_si = 0;
        p.B = gM; p.b_kcontig = 0; p.bs_row = Dd;
        p.b_so = (long long)Dd * Dd; p.b_si = 0;
        p.C = gt; p.cs_m = Dd; p.c_so = (long long)TOK * Dd; p.c_si = 0;
        p.bias = nullptr; p.bias_so = 0;
        p.M = TOK; p.N = Dd; p.K = Dd; p.zdiv = 1; p.causal = 0; p.klimit = 0;
        gemm_tf32_kernel<<<dim3(8, 32, Hh), 256, SMEM_B>>>(p);
    }
    // K3: Araw[z][n][m] = t_h[b,n,:] . x[b,m,:]   (per b,h: 1024x1024x1024, causal)
    {
        GemmP p{};
        p.A = gt; p.as_m = Dd;
        p.a_so = (long long)Nn * Dd;      // b
        p.a_si = (long long)TOK * Dd;     // h
        p.B = x; p.b_kcontig = 1; p.bs_row = Dd;
        p.b_so = (long long)Nn * Dd; p.b_si = 0;
        p.C = gA; p.cs_m = Nn;
        p.c_so = (long long)Hh * Nn * Nn; p.c_si = (long long)Nn * Nn;
        p.bias = nullptr; p.bias_so = 0;
        p.M = Nn; p.N = Nn; p.K = Dd; p.zdiv = Hh; p.causal = 1; p.klimit = 0;
        gemm_tf32_kernel<<<dim3(8, 8, Bb * Hh), 256, SMEM_B>>>(p);
    }
    // softmax with causal mask + scale + bias corrections
    softmax_kernel<<<Bb * Hh * Nn, 256>>>(gA, grq, grk, gc);

    // K4: v_h = X @ Wv_h + bv_h   (per head: 4096x64x1024)
    {
        GemmP p{};
        p.A = x; p.as_m = Dd; p.a_so = 0; p.a_si = 0;
        p.B = Wkqv + 2 * Dd; p.b_kcontig = 0; p.bs_row = Ee;
        p.b_so = (long long)Dd * Ee; p.b_si = 0;
        p.C = gv; p.cs_m = DHd; p.c_so = (long long)TOK * DHd; p.c_si = 0;
        p.bias = bkqv + 2 * Dd; p.bias_so = Ee;
        p.M = TOK; p.N = DHd; p.K = Dd; p.zdiv = 1; p.causal = 0; p.klimit = 0;
        gemm_tf32_kernel<<<dim3(1, 32, Hh), 256, SMEM_B>>>(p);
    }
    // K5: sa[b,n,h,:] = A[z] @ v[h,b]   (per b,h: 1024x64x1024, K limited by causality)
    {
        GemmP p{};
        p.A = gA; p.as_m = Nn;
        p.a_so = (long long)Hh * Nn * Nn; p.a_si = (long long)Nn * Nn;
        p.B = gv; p.b_kcontig = 0; p.bs_row = DHd;
        p.b_so = (long long)Nn * DHd;     // b
        p.b_si = (long long)TOK * DHd;    // h
        p.C = gsa; p.cs_m = Dd;
        p.c_so = (long long)Nn * Dd;      // b
        p.c_si = DHd;                     // h
        p.bias = nullptr; p.bias_so = 0;
        p.M = Nn; p.N = DHd; p.K = Nn; p.zdiv = Hh; p.causal = 0; p.klimit = 1;
        gemm_tf32_kernel<<<dim3(1, 8, Bb * Hh), 256, SMEM_B>>>(p);
    }
    // K6: out = sa @ Wp + bp   (4096x1024x1024)
    {
        GemmP p{};
        p.A = gsa; p.as_m = Dd; p.a_so = 0; p.a_si = 0;
        p.B = Wp; p.b_kcontig = 0; p.bs_row = Dd; p.b_so = 0; p.b_si = 0;
        p.C = out; p.cs_m = Dd; p.c_so = 0; p.c_si = 0;
        p.bias = bp; p.bias_so = 0;
        p.M = TOK; p.N = Dd; p.K = Dd; p.zdiv = 1; p.causal = 0; p.klimit = 0;
        gemm_tf32_kernel<<<dim3(8, 32, 1), 256, SMEM_B>>>(p);
    }
}

// round 4
// speedup vs baseline: 1.1285x; 1.1285x over previous
#include <cuda_runtime.h>
#include <cstdint>

// ---------------- problem constants ----------------
#define Dd   1024
#define Hh   16
#define DHd  64
#define Bb   4
#define Nn   1024
#define Ee   (2*Dd + DHd)      // 2112
#define TOK  (Bb*Nn)           // 4096

// ---------------- scratch (device globals; no allocs allowed) ----------------
__device__ float g_M   [(size_t)Hh*Dd*Dd];       //  64 MB  M' = M^T = Wk_h @ Wq_h^T
__device__ float g_t   [(size_t)Hh*TOK*Dd];      // 256 MB  t = x @ M_h
__device__ float g_Araw[(size_t)Bb*Hh*Nn*Nn];    // 256 MB  scores/probs
__device__ float g_vT  [(size_t)Hh*128*TOK];     //  33 MB  v^T  [h][dh(pad128)][tok]
__device__ float g_sa  [(size_t)TOK*Dd];         //  16 MB  sa
__device__ float g_x   [(size_t)TOK*Dd];         //  16 MB  tf32-rounded x
__device__ float g_wkqv[(size_t)Hh*Dd*Ee];       // 138 MB  tf32-rounded Wkqv
__device__ float g_WpT [(size_t)Dd*Dd];          //   4 MB  Wp^T rounded
__device__ float g_wvT [(size_t)Hh*128*Dd];      //   8 MB  Wv^T rounded [h][e(pad128)][d]
__device__ float g_u   [Hh*Dd];
__device__ float g_w   [Hh*Dd];
__device__ float g_c   [Hh];
__device__ float g_rq  [Bb*Hh*Nn];
__device__ float g_rk  [Bb*Hh*Nn];

// ---------------- tf32 helpers ----------------
__device__ __forceinline__ uint32_t f2tf32(float f) {
    uint32_t u;
    asm("cvt.rna.tf32.f32 %0, %1;" : "=r"(u) : "f"(f));
    return u;
}
__device__ __forceinline__ float roundtf(float f) {
    return __uint_as_float(f2tf32(f));
}

__device__ __forceinline__ void mma_tf32(float* d, const uint32_t* a, const uint32_t* b) {
    asm volatile(
        "mma.sync.aligned.m16n8k8.row.col.f32.tf32.tf32.f32 "
        "{%0,%1,%2,%3}, {%4,%5,%6,%7}, {%8,%9}, {%0,%1,%2,%3};\n"
        : "+f"(d[0]), "+f"(d[1]), "+f"(d[2]), "+f"(d[3])
        : "r"(a[0]), "r"(a[1]), "r"(a[2]), "r"(a[3]),
          "r"(b[0]), "r"(b[1]));
}

__device__ __forceinline__ void ldmx4(uint32_t* r, uint32_t addr) {
    asm volatile("ldmatrix.sync.aligned.m8n8.x4.shared.b16 {%0,%1,%2,%3}, [%4];"
                 : "=r"(r[0]), "=r"(r[1]), "=r"(r[2]), "=r"(r[3])
                 : "r"(addr));
}

__device__ __forceinline__ void cpa16(float* dst, const float* src) {
    uint32_t d = (uint32_t)__cvta_generic_to_shared(dst);
    asm volatile("cp.async.cg.shared.global [%0], [%1], 16;\n"
                 :: "r"(d), "l"(src));
}
__device__ __forceinline__ void cp_commit() {
    asm volatile("cp.async.commit_group;\n");
}
template<int N>
__device__ __forceinline__ void cp_wait() {
    asm volatile("cp.async.wait_group %0;\n" :: "n"(N));
}

// ---------------- generic batched GEMM (tf32, cp.async 3-stage, ldmatrix) ------
// C[z][m][n] = sum_k A[m,k] * B[n,k]  (+ bias[n])     [B always k-contiguous]
// Data in A/B must already be tf32-rounded.
struct GemmP {
    const float* A; const float* B; float* C; const float* bias;
    int as_m, bs_row, cs_m;
    long long a_so, a_si, b_so, b_si, c_so, c_si, bias_so;
    int M, N, K, zdiv;
    int causal;   // skip CTAs fully above the diagonal
    int klimit;   // K_eff = min(K, m0+BM)
    int ct;       // store C transposed: C[n*cs_m + m]
    int cround;   // round stored values to tf32
};

#define BM 128
#define BN 128
#define BK 32
#define TSTR 36                    // smem row stride (floats) for A and B tiles
#define A_TILE (BM*TSTR)           // 4608 floats
#define B_TILE (BN*TSTR)           // 4608 floats
#define STAGES 3
#define SMEM_FLOATS (STAGES*(A_TILE + B_TILE))   // 27648 floats = 110592 B

__global__ __launch_bounds__(256, 2) void gemm_tf32_kernel(GemmP p) {
    extern __shared__ float smem[];

    if (p.causal && ((int)blockIdx.x > (int)blockIdx.y)) return;

    const int z  = blockIdx.z;
    const long long zo = z / p.zdiv;
    const long long zi = z % p.zdiv;

    const float* Ab = p.A + zo * p.a_so + zi * p.a_si;
    const float* Bv = p.B + zo * p.b_so + zi * p.b_si;
    float*       Cb = p.C + zo * p.c_so + zi * p.c_si;

    const int m0 = blockIdx.y * BM;
    const int n0 = blockIdx.x * BN;

    const int tid  = threadIdx.x;
    const int warp = tid >> 5;
    const int lane = tid & 31;
    const int wm   = (warp >> 2) * 64;   // warp grid 2 x 4 over 128 x 128
    const int wn   = (warp & 3)  * 32;
    const int grp  = lane >> 2;
    const int t4   = lane & 3;

    const int K_eff = p.klimit ? min(p.K, m0 + BM) : p.K;
    const int nIter = K_eff / BK;

    // ---- loader coordinates: 128 rows x 8 chunks of 16B (same for A and B) ----
    const int l_r  = tid >> 3;
    const int l_kc = (tid & 7) * 4;
    const float* a_src0 = Ab + (size_t)(m0 + l_r) * p.as_m + l_kc;
    const float* b_src0 = Bv + (size_t)(n0 + l_r) * p.bs_row + l_kc;

    auto load_tiles = [&](int st, int k0) {
        {
            const float* src = a_src0 + k0;
            float* dst = smem + st * A_TILE + l_r * TSTR + l_kc;
#pragma unroll
            for (int i = 0; i < 4; i++) {
                cpa16(dst, src);
                src += (size_t)32 * p.as_m;
                dst += 32 * TSTR;
            }
        }
        {
            const float* src = b_src0 + k0;
            float* dst = smem + STAGES * A_TILE + st * B_TILE + l_r * TSTR + l_kc;
#pragma unroll
            for (int i = 0; i < 4; i++) {
                cpa16(dst, src);
                src += (size_t)32 * p.bs_row;
                dst += 32 * TSTR;
            }
        }
        cp_commit();
    };

    // ---- ldmatrix lane addressing (byte offsets within tile) ----
    // A (x4 per mt): matrices {rows R..R+7 kq0, R+8..R+15 kq0, R..R+7 kq1, R+8..+15 kq1}
    const uint32_t smem_u32 = (uint32_t)__cvta_generic_to_shared(smem);
    const uint32_t la_off = (uint32_t)((wm + (lane & 15)) * (TSTR * 4) + (lane >> 4) * 16);
    // B (x4 per pair p): {n NB..+7 kq0, n NB..+7 kq1, n NB+8..+15 kq0, n NB+8..+15 kq1}
    const uint32_t lb_off = (uint32_t)(STAGES * A_TILE * 4 +
                     (wn + (lane & 7) + ((lane >> 4) << 3)) * (TSTR * 4) +
                     ((lane >> 3) & 1) * 16);

    float acc[4][4][4];
#pragma unroll
    for (int i = 0; i < 4; i++)
#pragma unroll
        for (int j = 0; j < 4; j++)
#pragma unroll
            for (int r = 0; r < 4; r++) acc[i][j][r] = 0.f;

    load_tiles(0, 0);
    load_tiles(1, BK);

    for (int it = 0; it < nIter; it++) {
        const int st = it % STAGES;
        if (it + 2 < nIter) {
            load_tiles((it + 2) % STAGES, (it + 2) * BK);
            cp_wait<2>();
        } else if (it + 1 < nIter) {
            cp_wait<1>();
        } else {
            cp_wait<0>();
        }
        __syncthreads();

        const uint32_t aBase = smem_u32 + st * (A_TILE * 4) + la_off;
        const uint32_t bBase = smem_u32 + st * (B_TILE * 4) + lb_off;

#pragma unroll
        for (int ks = 0; ks < 4; ks++) {
            uint32_t a[4][4];
            uint32_t breg[2][4];
#pragma unroll
            for (int mt = 0; mt < 4; mt++)
                ldmx4(a[mt], aBase + mt * (16 * TSTR * 4) + ks * 32);
#pragma unroll
            for (int pp = 0; pp < 2; pp++)
                ldmx4(breg[pp], bBase + pp * (16 * TSTR * 4) + ks * 32);
#pragma unroll
            for (int mt = 0; mt < 4; mt++)
#pragma unroll
                for (int nt = 0; nt < 4; nt++)
                    mma_tf32(acc[mt][nt], a[mt], &breg[nt >> 1][(nt & 1) * 2]);
        }
        __syncthreads();
    }

    const float* biasb = nullptr;
    if (p.bias) biasb = p.bias + zo * p.bias_so;

#pragma unroll
    for (int mt = 0; mt < 4; mt++) {
#pragma unroll
        for (int nt = 0; nt < 4; nt++) {
            int c = n0 + wn + nt * 8 + t4 * 2;
            if (c >= p.N) continue;
            float b0 = 0.f, b1 = 0.f;
            if (biasb) { b0 = biasb[c]; b1 = biasb[c + 1]; }
#pragma unroll
            for (int rr = 0; rr < 2; rr++) {
                int row = m0 + wm + mt * 16 + grp + rr * 8;
                float v0 = acc[mt][nt][rr * 2]     + b0;
                float v1 = acc[mt][nt][rr * 2 + 1] + b1;
                if (p.cround) { v0 = roundtf(v0); v1 = roundtf(v1); }
                if (!p.ct) {
                    float2 v2; v2.x = v0; v2.y = v1;
                    *reinterpret_cast<float2*>(Cb + (size_t)row * p.cs_m + c) = v2;
                } else {
                    Cb[(size_t)c       * p.cs_m + row] = v0;
                    Cb[(size_t)(c + 1) * p.cs_m + row] = v1;
                }
            }
        }
    }
}

// ---------------- prepass kernels ----------------
__global__ void round_copy_kernel(const float4* __restrict__ src, float4* __restrict__ dst, int n4) {
    int i = blockIdx.x * blockDim.x + threadIdx.x;
    if (i < n4) {
        float4 v = src[i];
        v.x = roundtf(v.x); v.y = roundtf(v.y);
        v.z = roundtf(v.z); v.w = roundtf(v.w);
        dst[i] = v;
    }
}

// dst[c*drs + r] = round(src[r*srs + c]) ; per-z batch offsets
__global__ void transpose_round_kernel(const float* __restrict__ src, float* __restrict__ dst,
                                       int R, int C, int srs, int drs,
                                       long long s_bs, long long d_bs) {
    __shared__ float tile[32][33];
    src += (long long)blockIdx.z * s_bs;
    dst += (long long)blockIdx.z * d_bs;
    int r0 = blockIdx.y * 32, c0 = blockIdx.x * 32;
    int tx = threadIdx.x, ty = threadIdx.y;  // 32 x 8
#pragma unroll
    for (int i = 0; i < 32; i += 8) {
        int r = r0 + ty + i, c = c0 + tx;
        if (r < R && c < C) tile[ty + i][tx] = src[(size_t)r * srs + c];
    }
    __syncthreads();
#pragma unroll
    for (int i = 0; i < 32; i += 8) {
        int c = c0 + ty + i, r = r0 + tx;
        if (r < R && c < C) dst[(size_t)c * drs + r] = roundtf(tile[tx][ty + i]);
    }
}

// ---------------- bias-correction prep kernels (exact handling of bkqv) ----------------
__global__ void prep_uw_kernel(const float* __restrict__ Wkqv, const float* __restrict__ bkqv,
                               float* __restrict__ u, float* __restrict__ w) {
    int gw = (blockIdx.x * blockDim.x + threadIdx.x) >> 5;
    if (gw >= Hh * Dd) return;
    int lane = threadIdx.x & 31;
    int h = gw >> 10;
    int i = gw & (Dd - 1);
    const float* row = Wkqv + ((long long)h * Dd + i) * Ee;
    const float* bh  = bkqv + (long long)h * Ee;
    float s1 = 0.f, s2 = 0.f;
    for (int e = lane; e < Dd; e += 32) {
        s1 += row[Dd + e] * bh[e];
        s2 += row[e]      * bh[Dd + e];
    }
#pragma unroll
    for (int o = 16; o > 0; o >>= 1) {
        s1 += __shfl_xor_sync(0xffffffffu, s1, o);
        s2 += __shfl_xor_sync(0xffffffffu, s2, o);
    }
    if (lane == 0) { u[gw] = s1; w[gw] = s2; }
}

__global__ void prep_c_kernel(const float* __restrict__ bkqv, float* __restrict__ c) {
    int h = threadIdx.x >> 5;
    if (h >= Hh) return;
    int lane = threadIdx.x & 31;
    const float* bh = bkqv + (long long)h * Ee;
    float s = 0.f;
    for (int e = lane; e < Dd; e += 32) s += bh[Dd + e] * bh[e];
#pragma unroll
    for (int o = 16; o > 0; o >>= 1) s += __shfl_xor_sync(0xffffffffu, s, o);
    if (lane == 0) c[h] = s;
}

__global__ void prep_rqrk_kernel(const float* __restrict__ x, const float* __restrict__ u,
                                 const float* __restrict__ w, float* __restrict__ rq,
                                 float* __restrict__ rk) {
    int gw = (blockIdx.x * blockDim.x + threadIdx.x) >> 5;
    if (gw >= TOK * Hh) return;
    int lane = threadIdx.x & 31;
    int h   = gw & (Hh - 1);
    int tok = gw >> 4;
    const float* xr = x + (long long)tok * Dd;
    const float* uh = u + h * Dd;
    const float* wh = w + h * Dd;
    float s1 = 0.f, s2 = 0.f;
    for (int i = lane; i < Dd; i += 32) {
        float xv = xr[i];
        s1 += xv * uh[i];
        s2 += xv * wh[i];
    }
#pragma unroll
    for (int o = 16; o > 0; o >>= 1) {
        s1 += __shfl_xor_sync(0xffffffffu, s1, o);
        s2 += __shfl_xor_sync(0xffffffffu, s2, o);
    }
    if (lane == 0) {
        int b = tok >> 10, n = tok & (Nn - 1);
        int z = b * Hh + h;
        rq[z * Nn + n] = s1;
        rk[z * Nn + n] = s2;
    }
}

// ---------------- causal softmax: A = softmax((raw + rq_n + rk_m + c_h)/32) ----------------
__global__ void softmax_kernel(float* __restrict__ A, const float* __restrict__ rq,
                               const float* __restrict__ rk, const float* __restrict__ cvec) {
    const int row = blockIdx.x;
    const int z = row >> 10;
    const int n = row & (Nn - 1);
    const int h = z & (Hh - 1);
    float* rp = A + (long long)z * Nn * Nn + (long long)n * Nn;
    const float* rkz = rk + z * Nn;
    const float addn = rq[z * Nn + n] + cvec[h];
    const int tid = threadIdx.x;

    float l[4];
    float mx = -1e30f;
#pragma unroll
    for (int i = 0; i < 4; i++) {
        int m = tid + i * 256;
        float v = (m <= n) ? (rp[m] + addn + rkz[m]) * 0.03125f : -1e30f;
        l[i] = v;
        mx = fmaxf(mx, v);
    }
    __shared__ float red[256];
    red[tid] = mx; __syncthreads();
#pragma unroll
    for (int s = 128; s > 0; s >>= 1) {
        if (tid < s) red[tid] = fmaxf(red[tid], red[tid + s]);
        __syncthreads();
    }
    mx = red[0]; __syncthreads();

    float sum = 0.f;
#pragma unroll
    for (int i = 0; i < 4; i++) {
        float e = (l[i] > -1e29f) ? __expf(l[i] - mx) : 0.f;
        l[i] = e;
        sum += e;
    }
    red[tid] = sum; __syncthreads();
#pragma unroll
    for (int s = 128; s > 0; s >>= 1) {
        if (tid < s) red[tid] += red[tid + s];
        __syncthreads();
    }
    const float inv = 1.f / red[0];
#pragma unroll
    for (int i = 0; i < 4; i++) rp[tid + i * 256] = roundtf(l[i] * inv);
}

// ---------------- launch ----------------
extern "C" void kernel_launch(void* const* d_in, const int* in_sizes, int n_in,
                              void* d_out, int out_size) {
    const float* x    = (const float*)d_in[0];
    const float* Wkqv = (const float*)d_in[1];
    const float* bkqv = (const float*)d_in[2];
    const float* Wp   = (const float*)d_in[3];
    const float* bp   = (const float*)d_in[4];
    float* out = (float*)d_out;

    float *gM, *gt, *gA, *gvT, *gsa, *gx, *gwk, *gWpT, *gwvT, *gu, *gw, *gc, *grq, *grk;
    cudaGetSymbolAddress((void**)&gM,   g_M);
    cudaGetSymbolAddress((void**)&gt,   g_t);
    cudaGetSymbolAddress((void**)&gA,   g_Araw);
    cudaGetSymbolAddress((void**)&gvT,  g_vT);
    cudaGetSymbolAddress((void**)&gsa,  g_sa);
    cudaGetSymbolAddress((void**)&gx,   g_x);
    cudaGetSymbolAddress((void**)&gwk,  g_wkqv);
    cudaGetSymbolAddress((void**)&gWpT, g_WpT);
    cudaGetSymbolAddress((void**)&gwvT, g_wvT);
    cudaGetSymbolAddress((void**)&gu,   g_u);
    cudaGetSymbolAddress((void**)&gw,   g_w);
    cudaGetSymbolAddress((void**)&gc,   g_c);
    cudaGetSymbolAddress((void**)&grq,  g_rq);
    cudaGetSymbolAddress((void**)&grk,  g_rk);

    static int smem_set = 0;
    if (!smem_set) {
        cudaFuncSetAttribute(gemm_tf32_kernel,
                             cudaFuncAttributeMaxDynamicSharedMemorySize,
                             SMEM_FLOATS * 4);
        smem_set = 1;
    }
    const int SMEM_B = SMEM_FLOATS * 4;

    // ---- prepasses: tf32-round inputs, build transposed operands ----
    {
        int n4 = TOK * Dd / 4;
        round_copy_kernel<<<(n4 + 255) / 256, 256>>>((const float4*)x, (float4*)gx, n4);
    }
    {
        int n4 = Hh * Dd * Ee / 4;
        round_copy_kernel<<<(n4 + 255) / 256, 256>>>((const float4*)Wkqv, (float4*)gwk, n4);
    }
    // WpT[n][k] = round(Wp[k][n])
    transpose_round_kernel<<<dim3(32, 32, 1), dim3(32, 8)>>>(
        Wp, gWpT, Dd, Dd, Dd, Dd, 0, 0);
    // wvT[h][e][d] = round(Wkqv[h][d][2048+e])   (e padded to 128 rows, zeros)
    transpose_round_kernel<<<dim3(2, 32, Hh), dim3(32, 8)>>>(
        Wkqv + 2 * Dd, gwvT, Dd, DHd, Ee, Dd,
        (long long)Dd * Ee, (long long)128 * Dd);

    // bias-correction prep (exact, uses raw fp32 inputs)
    prep_uw_kernel<<<(Hh * Dd * 32 + 255) / 256, 256>>>(Wkqv, bkqv, gu, gw);
    prep_c_kernel<<<1, 512>>>(bkqv, gc);
    prep_rqrk_kernel<<<(TOK * Hh * 32 + 255) / 256, 256>>>(x, gu, gw, grq, grk);

    // K1: M'_h = Wk_h @ Wq_h^T  (= M_h^T)   per head 1024x1024x1024
    {
        GemmP p{};
        p.A = gwk;      p.as_m = Ee;  p.a_so = (long long)Dd * Ee; p.a_si = 0;
        p.B = gwk + Dd; p.bs_row = Ee; p.b_so = (long long)Dd * Ee; p.b_si = 0;
        p.C = gM; p.cs_m = Dd; p.c_so = (long long)Dd * Dd; p.c_si = 0;
        p.bias = nullptr; p.bias_so = 0;
        p.M = Dd; p.N = Dd; p.K = Dd; p.zdiv = 1;
        p.causal = 0; p.klimit = 0; p.ct = 0; p.cround = 1;
        gemm_tf32_kernel<<<dim3(8, 8, Hh), 256, SMEM_B>>>(p);
    }
    // K2: t_h = X @ M_h   (B = M'[j][d], k-contig)   per head 4096x1024x1024
    {
        GemmP p{};
        p.A = gx; p.as_m = Dd; p.a_so = 0; p.a_si = 0;
        p.B = gM; p.bs_row = Dd; p.b_so = (long long)Dd * Dd; p.b_si = 0;
        p.C = gt; p.cs_m = Dd; p.c_so = (long long)TOK * Dd; p.c_si = 0;
        p.bias = nullptr; p.bias_so = 0;
        p.M = TOK; p.N = Dd; p.K = Dd; p.zdiv = 1;
        p.causal = 0; p.klimit = 0; p.ct = 0; p.cround = 1;
        gemm_tf32_kernel<<<dim3(8, 32, Hh), 256, SMEM_B>>>(p);
    }
    // K3: Araw[z][n][m] = t_h[b,n,:] . x[b,m,:]   per (b,h) 1024x1024x1024, causal
    {
        GemmP p{};
        p.A = gt; p.as_m = Dd;
        p.a_so = (long long)Nn * Dd;       // b
        p.a_si = (long long)TOK * Dd;      // h
        p.B = gx; p.bs_row = Dd;
        p.b_so = (long long)Nn * Dd; p.b_si = 0;
        p.C = gA; p.cs_m = Nn;
        p.c_so = (long long)Hh * Nn * Nn; p.c_si = (long long)Nn * Nn;
        p.bias = nullptr; p.bias_so = 0;
        p.M = Nn; p.N = Nn; p.K = Dd; p.zdiv = Hh;
        p.causal = 1; p.klimit = 0; p.ct = 0; p.cround = 0;
        gemm_tf32_kernel<<<dim3(8, 8, Bb * Hh), 256, SMEM_B>>>(p);
    }
    // softmax with causal mask + scale + bias corrections (rounds probs to tf32)
    softmax_kernel<<<Bb * Hh * Nn, 256>>>(gA, grq, grk, gc);

    // K4: v^T_h = (X @ Wv_h + bv)^T   -> gvT[h][dh][tok]   per head 4096x64x1024
    {
        GemmP p{};
        p.A = gx; p.as_m = Dd; p.a_so = 0; p.a_si = 0;
        p.B = gwvT; p.bs_row = Dd; p.b_so = (long long)128 * Dd; p.b_si = 0;
        p.C = gvT; p.cs_m = TOK; p.c_so = (long long)128 * TOK; p.c_si = 0;
        p.bias = bkqv + 2 * Dd; p.bias_so = Ee;
        p.M = TOK; p.N = DHd; p.K = Dd; p.zdiv = 1;
        p.causal = 0; p.klimit = 0; p.ct = 1; p.cround = 1;
        gemm_tf32_kernel<<<dim3(1, 32, Hh), 256, SMEM_B>>>(p);
    }
    // K5: sa[b,n,h,:] = A[z] @ v[h,b]   (B = vT[dh][m], k-contig)  per (b,h) 1024x64x1024
    {
        GemmP p{};
        p.A = gA; p.as_m = Nn;
        p.a_so = (long long)Hh * Nn * Nn; p.a_si = (long long)Nn * Nn;
        p.B = gvT; p.bs_row = TOK;
        p.b_so = Nn;                       // b
        p.b_si = (long long)128 * TOK;     // h
        p.C = gsa; p.cs_m = Dd;
        p.c_so = (long long)Nn * Dd;       // b
        p.c_si = DHd;                      // h
        p.bias = nullptr; p.bias_so = 0;
        p.M = Nn; p.N = DHd; p.K = Nn; p.zdiv = Hh;
        p.causal = 0; p.klimit = 1; p.ct = 0; p.cround = 1;
        gemm_tf32_kernel<<<dim3(1, 8, Bb * Hh), 256, SMEM_B>>>(p);
    }
    // K6: out = sa @ Wp + bp   (B = WpT, k-contig)   4096x1024x1024
    {
        GemmP p{};
        p.A = gsa; p.as_m = Dd; p.a_so = 0; p.a_si = 0;
        p.B = gWpT; p.bs_row = Dd; p.b_so = 0; p.b_si = 0;
        p.C = out; p.cs_m = Dd; p.c_so = 0; p.c_si = 0;
        p.bias = bp; p.bias_so = 0;
        p.M = TOK; p.N = Dd; p.K = Dd; p.zdiv = 1;
        p.causal = 0; p.klimit = 0; p.ct = 0; p.cround = 0;
        gemm_tf32_kernel<<<dim3(8, 32, 1), 256, SMEM_B>>>(p);
    }
}

// round 7
// speedup vs baseline: 1.8604x; 1.6486x over previous
#include <cuda_runtime.h>
#include <cuda_fp16.h>
#include <cstdint>

// ---------------- problem constants ----------------
#define Dd   1024
#define Hh   16
#define DHd  64
#define Bb   4
#define Nn   1024
#define Ee   (2*Dd + DHd)      // 2112
#define TOK  (Bb*Nn)           // 4096

// ---------------- scratch (device globals; no allocs allowed) ----------------
__device__ __half g_M   [(size_t)Hh*Dd*Dd];      //  32 MB  M' = Wk_h @ Wq_h^T
__device__ __half g_t   [(size_t)Hh*TOK*Dd];     // 128 MB  t = x @ M_h
__device__ __half g_A   [(size_t)Bb*Hh*Nn*Nn];   // 128 MB  scores/probs
__device__ __half g_vT  [(size_t)Hh*128*TOK];    //  16 MB  v^T [h][dh(pad128)][tok]
__device__ __half g_sa  [(size_t)TOK*Dd];        //   8 MB  sa
__device__ __half g_x   [(size_t)TOK*Dd];        //   8 MB  half(x)
__device__ __half g_wkqv[(size_t)Hh*Dd*Ee];      //  69 MB  half(Wkqv)
__device__ __half g_WpT [(size_t)Dd*Dd];         //   2 MB  Wp^T
__device__ __half g_wvT [(size_t)Hh*128*Dd];     //   4 MB  Wv^T [h][e(pad128)][d]
__device__ float  g_u   [Hh*Dd];
__device__ float  g_w   [Hh*Dd];
__device__ float  g_c   [Hh];
__device__ float  g_rq  [Bb*Hh*Nn];
__device__ float  g_rk  [Bb*Hh*Nn];

// ---------------- helpers ----------------
__device__ __forceinline__ uint32_t smem_u32(const void* p) {
    uint32_t a;
    asm("{ .reg .u64 t; cvta.to.shared.u64 t, %1; cvt.u32.u64 %0, t; }"
        : "=r"(a) : "l"(p));
    return a;
}

__device__ __forceinline__ void mma_f16(float* d, const uint32_t* a, const uint32_t* b) {
    asm volatile(
        "mma.sync.aligned.m16n8k16.row.col.f32.f16.f16.f32 "
        "{%0,%1,%2,%3}, {%4,%5,%6,%7}, {%8,%9}, {%0,%1,%2,%3};\n"
        : "+f"(d[0]), "+f"(d[1]), "+f"(d[2]), "+f"(d[3])
        : "r"(a[0]), "r"(a[1]), "r"(a[2]), "r"(a[3]),
          "r"(b[0]), "r"(b[1]));
}

__device__ __forceinline__ void ldmx4(uint32_t* r, uint32_t addr) {
    asm volatile("ldmatrix.sync.aligned.m8n8.x4.shared.b16 {%0,%1,%2,%3}, [%4];"
                 : "=r"(r[0]), "=r"(r[1]), "=r"(r[2]), "=r"(r[3])
                 : "r"(addr));
}

__device__ __forceinline__ void cpa16(uint32_t dst_smem, const void* src) {
    asm volatile("cp.async.cg.shared.global [%0], [%1], 16;\n"
                 :: "r"(dst_smem), "l"(src));
}
__device__ __forceinline__ void cp_commit() {
    asm volatile("cp.async.commit_group;\n");
}
template<int N>
__device__ __forceinline__ void cp_wait() {
    asm volatile("cp.async.wait_group %0;\n" :: "n"(N));
}

// ---------------- fp16 batched GEMM (m16n8k16, cp.async 3-stage, ldmatrix) -----
// C[z][m][n] = sum_k A[m,k] * B[n,k]  (+ bias[n])   [A,B half, k-contiguous]
struct GemmP {
    const __half* A; const __half* B; void* C; const float* bias;
    int as_m, bs_row, cs_m;
    long long a_so, a_si, b_so, b_si, c_so, c_si, bias_so;
    int M, N, K, zdiv;
    int causal;   // skip CTAs fully above the diagonal
    int klimit;   // K_eff = min(K, m0+128)
    int ct;       // store C transposed (half only)
    int cf32;     // C is float (else half)
};

#define BM 128
#define BN 128
#define BK 64
#define ROWB 144                       // smem row stride bytes (64 halves + 8 pad)
#define TILE_BYTES (BM*ROWB)           // 18432
#define STAGES 3
#define SMEM_BYTES (STAGES*2*TILE_BYTES)   // 110592

__global__ __launch_bounds__(256, 2) void gemm_f16_kernel(GemmP p) {
    extern __shared__ char smem[];

    if (p.causal && ((int)blockIdx.x > (int)blockIdx.y)) return;

    const int z  = blockIdx.z;
    const long long zo = z / p.zdiv;
    const long long zi = z % p.zdiv;

    const __half* Ab = p.A + zo * p.a_so + zi * p.a_si;
    const __half* Bv = p.B + zo * p.b_so + zi * p.b_si;

    const int m0 = blockIdx.y * BM;
    const int n0 = blockIdx.x * BN;
    const int nColsB = min(BN, p.N - n0);

    const int tid  = threadIdx.x;
    const int warp = tid >> 5;
    const int lane = tid & 31;
    const int wm   = (warp >> 2) * 64;   // warp grid 2 x 4 over 128 x 128
    const int wn   = (warp & 3)  * 32;
    const int grp  = lane >> 2;
    const int t4   = lane & 3;

    const int K_eff = p.klimit ? min(p.K, m0 + BM) : p.K;
    const int nIter = K_eff / BK;

    const uint32_t sbase = smem_u32(smem);

    auto load_tiles = [&](int st, int k0) {
        const uint32_t abase = sbase + st * (2 * TILE_BYTES);
#pragma unroll
        for (int i = 0; i < 4; i++) {
            int ch = tid + i * 256;
            int row = ch >> 3, c = ch & 7;
            cpa16(abase + row * ROWB + c * 16,
                  Ab + (size_t)(m0 + row) * p.as_m + k0 + c * 8);
        }
        const uint32_t bbase = abase + TILE_BYTES;
#pragma unroll
        for (int i = 0; i < 4; i++) {
            int ch = tid + i * 256;
            int row = ch >> 3, c = ch & 7;
            if (row < nColsB)
                cpa16(bbase + row * ROWB + c * 16,
                      Bv + (size_t)(n0 + row) * p.bs_row + k0 + c * 8);
        }
        cp_commit();
    };

    // ldmatrix lane addressing (byte offsets within tile)
    const uint32_t la_off = (uint32_t)((wm + (lane & 15)) * ROWB + (lane >> 4) * 16);
    const uint32_t lb_off = (uint32_t)(TILE_BYTES +
                     (wn + (lane & 7) + ((lane >> 4) << 3)) * ROWB +
                     ((lane >> 3) & 1) * 16);

    float acc[4][4][4];
#pragma unroll
    for (int i = 0; i < 4; i++)
#pragma unroll
        for (int j = 0; j < 4; j++)
#pragma unroll
            for (int r = 0; r < 4; r++) acc[i][j][r] = 0.f;

    load_tiles(0, 0);
    load_tiles(1, BK);

    for (int it = 0; it < nIter; it++) {
        const int st = it % STAGES;
        if (it + 2 < nIter) {
            load_tiles((it + 2) % STAGES, (it + 2) * BK);
            cp_wait<2>();
        } else if (it + 1 < nIter) {
            cp_wait<1>();
        } else {
            cp_wait<0>();
        }
        __syncthreads();

        const uint32_t aBase = sbase + st * (2 * TILE_BYTES) + la_off;
        const uint32_t bBase = sbase + st * (2 * TILE_BYTES) + lb_off;

#pragma unroll
        for (int ks = 0; ks < 4; ks++) {      // 4 x k16 = BK
            uint32_t a[4][4];
            uint32_t breg[2][4];
#pragma unroll
            for (int mt = 0; mt < 4; mt++)
                ldmx4(a[mt], aBase + mt * (16 * ROWB) + ks * 32);
#pragma unroll
            for (int pp = 0; pp < 2; pp++)
                ldmx4(breg[pp], bBase + pp * (16 * ROWB) + ks * 32);
#pragma unroll
            for (int mt = 0; mt < 4; mt++)
#pragma unroll
                for (int nt = 0; nt < 4; nt++)
                    mma_f16(acc[mt][nt], a[mt], &breg[nt >> 1][(nt & 1) * 2]);
        }
        __syncthreads();
    }

    const float* biasb = p.bias ? (p.bias + zo * p.bias_so) : nullptr;

    if (p.cf32) {
        float* Cb = (float*)p.C + zo * p.c_so + zi * p.c_si;
#pragma unroll
        for (int mt = 0; mt < 4; mt++) {
#pragma unroll
            for (int nt = 0; nt < 4; nt++) {
                int c = n0 + wn + nt * 8 + t4 * 2;
                if (c >= p.N) continue;
                float b0 = 0.f, b1 = 0.f;
                if (biasb) { b0 = biasb[c]; b1 = biasb[c + 1]; }
#pragma unroll
                for (int rr = 0; rr < 2; rr++) {
                    int row = m0 + wm + mt * 16 + grp + rr * 8;
                    float2 v2;
                    v2.x = acc[mt][nt][rr * 2]     + b0;
                    v2.y = acc[mt][nt][rr * 2 + 1] + b1;
                    *reinterpret_cast<float2*>(Cb + (size_t)row * p.cs_m + c) = v2;
                }
            }
        }
    } else {
        __half* Cb = (__half*)p.C + zo * p.c_so + zi * p.c_si;
#pragma unroll
        for (int mt = 0; mt < 4; mt++) {
#pragma unroll
            for (int nt = 0; nt < 4; nt++) {
                int c = n0 + wn + nt * 8 + t4 * 2;
                if (c >= p.N) continue;
                float b0 = 0.f, b1 = 0.f;
                if (biasb) { b0 = biasb[c]; b1 = biasb[c + 1]; }
#pragma unroll
                for (int rr = 0; rr < 2; rr++) {
                    int row = m0 + wm + mt * 16 + grp + rr * 8;
                    float v0 = acc[mt][nt][rr * 2]     + b0;
                    float v1 = acc[mt][nt][rr * 2 + 1] + b1;
                    if (!p.ct) {
                        *reinterpret_cast<__half2*>(Cb + (size_t)row * p.cs_m + c) =
                            __floats2half2_rn(v0, v1);
                    } else {
                        Cb[(size_t)c       * p.cs_m + row] = __float2half_rn(v0);
                        Cb[(size_t)(c + 1) * p.cs_m + row] = __float2half_rn(v1);
                    }
                }
            }
        }
    }
}

// ---------------- prepass kernels ----------------
__global__ void f2h_kernel(const float4* __restrict__ src, __half2* __restrict__ dst, int n4) {
    int i = blockIdx.x * blockDim.x + threadIdx.x;
    if (i < n4) {
        float4 v = src[i];
        dst[2 * i]     = __floats2half2_rn(v.x, v.y);
        dst[2 * i + 1] = __floats2half2_rn(v.z, v.w);
    }
}

// dst[c*drs + r] = half(src[r*srs + c]) ; per-z batch offsets
__global__ void transpose_h_kernel(const float* __restrict__ src, __half* __restrict__ dst,
                                   int R, int C, int srs, int drs,
                                   long long s_bs, long long d_bs) {
    __shared__ float tile[32][33];
    src += (long long)blockIdx.z * s_bs;
    dst += (long long)blockIdx.z * d_bs;
    int r0 = blockIdx.y * 32, c0 = blockIdx.x * 32;
    int tx = threadIdx.x, ty = threadIdx.y;  // 32 x 8
#pragma unroll
    for (int i = 0; i < 32; i += 8) {
        int r = r0 + ty + i, c = c0 + tx;
        if (r < R && c < C) tile[ty + i][tx] = src[(size_t)r * srs + c];
    }
    __syncthreads();
#pragma unroll
    for (int i = 0; i < 32; i += 8) {
        int c = c0 + ty + i, r = r0 + tx;
        if (r < R && c < C) dst[(size_t)c * drs + r] = __float2half_rn(tile[tx][ty + i]);
    }
}

// ---------------- bias-correction prep kernels (exact, fp32 inputs) ----------------
__global__ void prep_uw_kernel(const float* __restrict__ Wkqv, const float* __restrict__ bkqv,
                               float* __restrict__ u, float* __restrict__ w) {
    int gw = (blockIdx.x * blockDim.x + threadIdx.x) >> 5;
    if (gw >= Hh * Dd) return;
    int lane = threadIdx.x & 31;
    int h = gw >> 10;
    int i = gw & (Dd - 1);
    const float* row = Wkqv + ((long long)h * Dd + i) * Ee;
    const float* bh  = bkqv + (long long)h * Ee;
    float s1 = 0.f, s2 = 0.f;
    for (int e = lane; e < Dd; e += 32) {
        s1 += row[Dd + e] * bh[e];
        s2 += row[e]      * bh[Dd + e];
    }
#pragma unroll
    for (int o = 16; o > 0; o >>= 1) {
        s1 += __shfl_xor_sync(0xffffffffu, s1, o);
        s2 += __shfl_xor_sync(0xffffffffu, s2, o);
    }
    if (lane == 0) { u[gw] = s1; w[gw] = s2; }
}

__global__ void prep_c_kernel(const float* __restrict__ bkqv, float* __restrict__ c) {
    int h = threadIdx.x >> 5;
    if (h >= Hh) return;
    int lane = threadIdx.x & 31;
    const float* bh = bkqv + (long long)h * Ee;
    float s = 0.f;
    for (int e = lane; e < Dd; e += 32) s += bh[Dd + e] * bh[e];
#pragma unroll
    for (int o = 16; o > 0; o >>= 1) s += __shfl_xor_sync(0xffffffffu, s, o);
    if (lane == 0) c[h] = s;
}

__global__ void prep_rqrk_kernel(const float* __restrict__ x, const float* __restrict__ u,
                                 const float* __restrict__ w, float* __restrict__ rq,
                                 float* __restrict__ rk) {
    int gw = (blockIdx.x * blockDim.x + threadIdx.x) >> 5;
    if (gw >= TOK * Hh) return;
    int lane = threadIdx.x & 31;
    int h   = gw & (Hh - 1);
    int tok = gw >> 4;
    const float* xr = x + (long long)tok * Dd;
    const float* uh = u + h * Dd;
    const float* wh = w + h * Dd;
    float s1 = 0.f, s2 = 0.f;
    for (int i = lane; i < Dd; i += 32) {
        float xv = xr[i];
        s1 += xv * uh[i];
        s2 += xv * wh[i];
    }
#pragma unroll
    for (int o = 16; o > 0; o >>= 1) {
        s1 += __shfl_xor_sync(0xffffffffu, s1, o);
        s2 += __shfl_xor_sync(0xffffffffu, s2, o);
    }
    if (lane == 0) {
        int b = tok >> 10, n = tok & (Nn - 1);
        int z = b * Hh + h;
        rq[z * Nn + n] = s1;
        rk[z * Nn + n] = s2;
    }
}

// ---------------- causal softmax: A = softmax((raw + rq_n + rk_m + c_h)/32) ----------------
__global__ void softmax_kernel(__half* __restrict__ A, const float* __restrict__ rq,
                               const float* __restrict__ rk, const float* __restrict__ cvec) {
    const int row = blockIdx.x;
    const int z = row >> 10;
    const int n = row & (Nn - 1);
    const int h = z & (Hh - 1);
    __half* rp = A + (long long)z * Nn * Nn + (long long)n * Nn;
    const float* rkz = rk + z * Nn;
    const float addn = rq[z * Nn + n] + cvec[h];
    const int tid = threadIdx.x;

    float l[4];
    float mx = -1e30f;
#pragma unroll
    for (int i = 0; i < 4; i++) {
        int m = tid + i * 256;
        float v = (m <= n) ? (__half2float(rp[m]) + addn + rkz[m]) * 0.03125f : -1e30f;
        l[i] = v;
        mx = fmaxf(mx, v);
    }
    __shared__ float red[256];
    red[tid] = mx; __syncthreads();
#pragma unroll
    for (int s = 128; s > 0; s >>= 1) {
        if (tid < s) red[tid] = fmaxf(red[tid], red[tid + s]);
        __syncthreads();
    }
    mx = red[0]; __syncthreads();

    float sum = 0.f;
#pragma unroll
    for (int i = 0; i < 4; i++) {
        float e = (l[i] > -1e29f) ? __expf(l[i] - mx) : 0.f;
        l[i] = e;
        sum += e;
    }
    red[tid] = sum; __syncthreads();
#pragma unroll
    for (int s = 128; s > 0; s >>= 1) {
        if (tid < s) red[tid] += red[tid + s];
        __syncthreads();
    }
    const float inv = 1.f / red[0];
#pragma unroll
    for (int i = 0; i < 4; i++) rp[tid + i * 256] = __float2half_rn(l[i] * inv);
}

// ---------------- launch ----------------
extern "C" void kernel_launch(void* const* d_in, const int* in_sizes, int n_in,
                              void* d_out, int out_size) {
    const float* x    = (const float*)d_in[0];
    const float* Wkqv = (const float*)d_in[1];
    const float* bkqv = (const float*)d_in[2];
    const float* Wp   = (const float*)d_in[3];
    const float* bp   = (const float*)d_in[4];
    float* out = (float*)d_out;

    __half *gM, *gt, *gA, *gvT, *gsa, *gx, *gwk, *gWpT, *gwvT;
    float *gu, *gw, *gc, *grq, *grk;
    cudaGetSymbolAddress((void**)&gM,   g_M);
    cudaGetSymbolAddress((void**)&gt,   g_t);
    cudaGetSymbolAddress((void**)&gA,   g_A);
    cudaGetSymbolAddress((void**)&gvT,  g_vT);
    cudaGetSymbolAddress((void**)&gsa,  g_sa);
    cudaGetSymbolAddress((void**)&gx,   g_x);
    cudaGetSymbolAddress((void**)&gwk,  g_wkqv);
    cudaGetSymbolAddress((void**)&gWpT, g_WpT);
    cudaGetSymbolAddress((void**)&gwvT, g_wvT);
    cudaGetSymbolAddress((void**)&gu,   g_u);
    cudaGetSymbolAddress((void**)&gw,   g_w);
    cudaGetSymbolAddress((void**)&gc,   g_c);
    cudaGetSymbolAddress((void**)&grq,  g_rq);
    cudaGetSymbolAddress((void**)&grk,  g_rk);

    static int smem_set = 0;
    if (!smem_set) {
        cudaFuncSetAttribute(gemm_f16_kernel,
                             cudaFuncAttributeMaxDynamicSharedMemorySize, SMEM_BYTES);
        smem_set = 1;
    }

    // ---- prepasses: half conversions + transposed operands ----
    {
        int n4 = TOK * Dd / 4;
        f2h_kernel<<<(n4 + 255) / 256, 256>>>((const float4*)x, (__half2*)gx, n4);
    }
    {
        int n4 = Hh * Dd * Ee / 4;
        f2h_kernel<<<(n4 + 255) / 256, 256>>>((const float4*)Wkqv, (__half2*)gwk, n4);
    }
    transpose_h_kernel<<<dim3(32, 32, 1), dim3(32, 8)>>>(
        Wp, gWpT, Dd, Dd, Dd, Dd, 0, 0);
    transpose_h_kernel<<<dim3(2, 32, Hh), dim3(32, 8)>>>(
        Wkqv + 2 * Dd, gwvT, Dd, DHd, Ee, Dd,
        (long long)Dd * Ee, (long long)128 * Dd);

    prep_uw_kernel<<<(Hh * Dd * 32 + 255) / 256, 256>>>(Wkqv, bkqv, gu, gw);
    prep_c_kernel<<<1, 512>>>(bkqv, gc);
    prep_rqrk_kernel<<<(TOK * Hh * 32 + 255) / 256, 256>>>(x, gu, gw, grq, grk);

    // K1: M'_h = Wk_h @ Wq_h^T   per head 1024x1024x1024
    {
        GemmP p{};
        p.A = gwk;      p.as_m = Ee;   p.a_so = (long long)Dd * Ee; p.a_si = 0;
        p.B = gwk + Dd; p.bs_row = Ee; p.b_so = (long long)Dd * Ee; p.b_si = 0;
        p.C = gM; p.cs_m = Dd; p.c_so = (long long)Dd * Dd; p.c_si = 0;
        p.bias = nullptr; p.bias_so = 0;
        p.M = Dd; p.N = Dd; p.K = Dd; p.zdiv = 1;
        p.causal = 0; p.klimit = 0; p.ct = 0; p.cf32 = 0;
        gemm_f16_kernel<<<dim3(8, 8, Hh), 256, SMEM_BYTES>>>(p);
    }
    // K2: t_h = X @ M_h   per head 4096x1024x1024
    {
        GemmP p{};
        p.A = gx; p.as_m = Dd; p.a_so = 0; p.a_si = 0;
        p.B = gM; p.bs_row = Dd; p.b_so = (long long)Dd * Dd; p.b_si = 0;
        p.C = gt; p.cs_m = Dd; p.c_so = (long long)TOK * Dd; p.c_si = 0;
        p.bias = nullptr; p.bias_so = 0;
        p.M = TOK; p.N = Dd; p.K = Dd; p.zdiv = 1;
        p.causal = 0; p.klimit = 0; p.ct = 0; p.cf32 = 0;
        gemm_f16_kernel<<<dim3(8, 32, Hh), 256, SMEM_BYTES>>>(p);
    }
    // K3: A[z][n][m] = t_h[b,n,:] . x[b,m,:]   per (b,h), causal
    {
        GemmP p{};
        p.A = gt; p.as_m = Dd;
        p.a_so = (long long)Nn * Dd;
        p.a_si = (long long)TOK * Dd;
        p.B = gx; p.bs_row = Dd;
        p.b_so = (long long)Nn * Dd; p.b_si = 0;
        p.C = gA; p.cs_m = Nn;
        p.c_so = (long long)Hh * Nn * Nn; p.c_si = (long long)Nn * Nn;
        p.bias = nullptr; p.bias_so = 0;
        p.M = Nn; p.N = Nn; p.K = Dd; p.zdiv = Hh;
        p.causal = 1; p.klimit = 0; p.ct = 0; p.cf32 = 0;
        gemm_f16_kernel<<<dim3(8, 8, Bb * Hh), 256, SMEM_BYTES>>>(p);
    }
    softmax_kernel<<<Bb * Hh * Nn, 256>>>(gA, grq, grk, gc);

    // K4: v^T_h = (X @ Wv_h + bv)^T -> gvT[h][dh][tok]   per head 4096x64x1024
    {
        GemmP p{};
        p.A = gx; p.as_m = Dd; p.a_so = 0; p.a_si = 0;
        p.B = gwvT; p.bs_row = Dd; p.b_so = (long long)128 * Dd; p.b_si = 0;
        p.C = gvT; p.cs_m = TOK; p.c_so = (long long)128 * TOK; p.c_si = 0;
        p.bias = bkqv + 2 * Dd; p.bias_so = Ee;
        p.M = TOK; p.N = DHd; p.K = Dd; p.zdiv = 1;
        p.causal = 0; p.klimit = 0; p.ct = 1; p.cf32 = 0;
        gemm_f16_kernel<<<dim3(1, 32, Hh), 256, SMEM_BYTES>>>(p);
    }
    // K5: sa[b,n,h,:] = A[z] @ v[h,b]   per (b,h) 1024x64x1024, K causally limited
    {
        GemmP p{};
        p.A = gA; p.as_m = Nn;
        p.a_so = (long long)Hh * Nn * Nn; p.a_si = (long long)Nn * Nn;
        p.B = gvT; p.bs_row = TOK;
        p.b_so = Nn;
        p.b_si = (long long)128 * TOK;
        p.C = gsa; p.cs_m = Dd;
        p.c_so = (long long)Nn * Dd;
        p.c_si = DHd;
        p.bias = nullptr; p.bias_so = 0;
        p.M = Nn; p.N = DHd; p.K = Nn; p.zdiv = Hh;
        p.causal = 0; p.klimit = 1; p.ct = 0; p.cf32 = 0;
        gemm_f16_kernel<<<dim3(1, 8, Bb * Hh), 256, SMEM_BYTES>>>(p);
    }
    // K6: out = sa @ Wp + bp   4096x1024x1024  (fp32 output)
    {
        GemmP p{};
        p.A = gsa; p.as_m = Dd; p.a_so = 0; p.a_si = 0;
        p.B = gWpT; p.bs_row = Dd; p.b_so = 0; p.b_si = 0;
        p.C = out; p.cs_m = Dd; p.c_so = 0; p.c_si = 0;
        p.bias = bp; p.bias_so = 0;
        p.M = TOK; p.N = Dd; p.K = Dd; p.zdiv = 1;
        p.causal = 0; p.klimit = 0; p.ct = 0; p.cf32 = 1;
        gemm_f16_kernel<<<dim3(8, 32, 1), 256, SMEM_BYTES>>>(p);
    }
}